// round 4
// baseline (speedup 1.0000x reference)
#include <cuda_runtime.h>
#include <cstdint>

// ---------------------------------------------------------------------------
// MyGraphConv: out = relu([h[:n_dst] || segment_mean(h[edge_src], edge_dst)] @ W.T + b)
// Shapes: h[100000,128] f32, E=600000 edges, W[128,256] f32, b[128] f32,
//         out[n_dst=20000,128] f32.
//
// Plan:
//   K0 detect : device-side int32-vs-int64 edge dtype probe -> g_is64
//   K1 zero   : clear g_agg (n_dst x 128) and g_deg (n_dst)
//   K2 edge   : 1 warp / edge; gather h[src] row (float4/lane),
//               red.global.add.v4.f32 into g_agg[dst], lane0 bumps g_deg[dst]
//   K3 gemm   : 128x128 tile SGEMM over K=256; K<128 reads h, K>=128 reads
//               g_agg scaled by 1/max(deg,1) (mean fused into the tile load);
//               epilogue adds bias + relu.
// Scratch via __device__ globals (no allocations). All launches only ->
// graph-capturable.
// ---------------------------------------------------------------------------

#define MAX_DST 32768
#define DIMD    128
#define OUTN    128
#define KDIM    256

__device__ float g_agg[(size_t)MAX_DST * DIMD];
__device__ float g_deg[MAX_DST];
__device__ int   g_is64;

// --- K0: edge index dtype detection -----------------------------------------
// If the buffers hold int64, every sampled 8-byte word is a valid index
// (< n_src / n_dst). If they hold int32, an 8-byte read combines two indices
// and (except w/ prob ~1e-5 per sample) exceeds 2^32. Sample only the first
// E/2 int64 slots so the read stays inside the buffer for EITHER dtype.
__global__ void detect_kernel(const void* esrc, const void* edst,
                              int E, int n_src, int n_dst) {
    if (threadIdx.x != 0 || blockIdx.x != 0) return;
    const unsigned long long* p = (const unsigned long long*)esrc;
    const unsigned long long* q = (const unsigned long long*)edst;
    int lim = E >> 1;
    if (lim < 1) { g_is64 = 0; return; }
    int step = (lim > 64) ? (lim / 64) : 1;
    int ok = 1;
    for (int i = 0; i < lim; i += step) {
        if (p[i] >= (unsigned long long)n_src) { ok = 0; break; }
        if (q[i] >= (unsigned long long)n_dst) { ok = 0; break; }
    }
    g_is64 = ok;
}

// --- K1: zero scratch --------------------------------------------------------
__global__ void zero_kernel(int n_dst) {
    int total = n_dst * DIMD;
    int stride = gridDim.x * blockDim.x;
    for (int i = blockIdx.x * blockDim.x + threadIdx.x; i < total; i += stride)
        g_agg[i] = 0.0f;
    for (int i = blockIdx.x * blockDim.x + threadIdx.x; i < n_dst; i += stride)
        g_deg[i] = 0.0f;
}

// --- K2: edge aggregation (1 warp per edge) ----------------------------------
__global__ void edge_agg_kernel(const float* __restrict__ h,
                                const void* __restrict__ esrc,
                                const void* __restrict__ edst,
                                int E) {
    int gw   = (int)((blockIdx.x * (unsigned)blockDim.x + threadIdx.x) >> 5);
    int lane = threadIdx.x & 31;
    if (gw >= E) return;

    long long s, d;
    if (g_is64) {
        s = ((const long long*)esrc)[gw];
        d = ((const long long*)edst)[gw];
    } else {
        s = (long long)((const int*)esrc)[gw];
        d = (long long)((const int*)edst)[gw];
    }

    float4 v = ((const float4*)(h + s * DIMD))[lane];
    float* a = g_agg + d * DIMD + lane * 4;
    asm volatile("red.global.add.v4.f32 [%0], {%1,%2,%3,%4};"
                 :: "l"(a), "f"(v.x), "f"(v.y), "f"(v.z), "f"(v.w)
                 : "memory");
    if (lane == 0) atomicAdd(&g_deg[d], 1.0f);
}

// --- K3: fused concat + mean + SGEMM + bias + relu ---------------------------
// out[m][n] = relu( sum_{k<128} h[m][k]*W[n][k]
//                 + sum_{k>=128} (agg[m][k-128]/max(deg[m],1))*W[n][k] + b[n] )
#define BM 128
#define BN 128
#define BK 16
#define TM 8
#define TN 8

__global__ __launch_bounds__(256, 2)
void gemm_kernel(const float* __restrict__ h,
                 const float* __restrict__ W,
                 const float* __restrict__ b,
                 float* __restrict__ out,
                 int n_dst) {
    __shared__ float Zs[BK][BM];
    __shared__ float Ws[BK][BN];

    const int tid  = threadIdx.x;            // 0..255
    const int tx   = tid & 15;                // column group (n)
    const int ty   = tid >> 4;                // row group (m)
    const int row0 = blockIdx.x * BM;

    float acc[TM][TN];
#pragma unroll
    for (int i = 0; i < TM; i++)
#pragma unroll
        for (int j = 0; j < TN; j++) acc[i][j] = 0.0f;

    for (int kk = 0; kk < KDIM; kk += BK) {
        const bool neigh = (kk >= DIMD);
        const float* __restrict__ srcZ = neigh ? g_agg : h;
        const int kbase = neigh ? (kk - DIMD) : kk;

        // Load Z tile: BK*BM = 2048 floats = 512 float4, 2 per thread.
#pragma unroll
        for (int i = 0; i < 2; i++) {
            int li = tid + i * 256;
            int m  = li >> 2;                 // 0..127
            int k4 = (li & 3) * 4;            // 0,4,8,12
            int row = row0 + m;
            float4 v = make_float4(0.f, 0.f, 0.f, 0.f);
            if (row < n_dst) {
                v = *(const float4*)(srcZ + (size_t)row * DIMD + kbase + k4);
                if (neigh) {
                    float inv = 1.0f / fmaxf(g_deg[row], 1.0f);
                    v.x *= inv; v.y *= inv; v.z *= inv; v.w *= inv;
                }
            }
            Zs[k4 + 0][m] = v.x;
            Zs[k4 + 1][m] = v.y;
            Zs[k4 + 2][m] = v.z;
            Zs[k4 + 3][m] = v.w;
        }

        // Load W tile: Ws[k][n] = W[n*KDIM + kk + k]
#pragma unroll
        for (int i = 0; i < 2; i++) {
            int li = tid + i * 256;
            int n  = li >> 2;                 // 0..127
            int k4 = (li & 3) * 4;
            float4 v = *(const float4*)(W + (size_t)n * KDIM + kk + k4);
            Ws[k4 + 0][n] = v.x;
            Ws[k4 + 1][n] = v.y;
            Ws[k4 + 2][n] = v.z;
            Ws[k4 + 3][n] = v.w;
        }

        __syncthreads();

#pragma unroll
        for (int k = 0; k < BK; k++) {
            float zr[TM], wr[TN];
            *(float4*)&zr[0] = *(const float4*)&Zs[k][ty * TM];
            *(float4*)&zr[4] = *(const float4*)&Zs[k][ty * TM + 4];
            *(float4*)&wr[0] = *(const float4*)&Ws[k][tx * TN];
            *(float4*)&wr[4] = *(const float4*)&Ws[k][tx * TN + 4];
#pragma unroll
            for (int i = 0; i < TM; i++)
#pragma unroll
                for (int j = 0; j < TN; j++)
                    acc[i][j] = fmaf(zr[i], wr[j], acc[i][j]);
        }

        __syncthreads();
    }

    // Epilogue: bias + relu, float4 stores.
    float bias[TN];
#pragma unroll
    for (int j = 0; j < TN; j++) bias[j] = b[tx * TN + j];

#pragma unroll
    for (int i = 0; i < TM; i++) {
        int row = row0 + ty * TM + i;
        if (row < n_dst) {
            float4 o0, o1;
            o0.x = fmaxf(acc[i][0] + bias[0], 0.f);
            o0.y = fmaxf(acc[i][1] + bias[1], 0.f);
            o0.z = fmaxf(acc[i][2] + bias[2], 0.f);
            o0.w = fmaxf(acc[i][3] + bias[3], 0.f);
            o1.x = fmaxf(acc[i][4] + bias[4], 0.f);
            o1.y = fmaxf(acc[i][5] + bias[5], 0.f);
            o1.z = fmaxf(acc[i][6] + bias[6], 0.f);
            o1.w = fmaxf(acc[i][7] + bias[7], 0.f);
            float* op = out + (size_t)row * OUTN + tx * TN;
            *(float4*)(op)     = o0;
            *(float4*)(op + 4) = o1;
        }
    }
}

// ---------------------------------------------------------------------------
extern "C" void kernel_launch(void* const* d_in, const int* in_sizes, int n_in,
                              void* d_out, int out_size) {
    const float* h    = (const float*)d_in[0];
    const void*  esrc = d_in[1];
    const void*  edst = d_in[2];
    const float* W    = (const float*)d_in[3];
    const float* b    = (const float*)d_in[4];
    float*       out  = (float*)d_out;

    int n_dst = out_size / OUTN;            // 20000
    if (n_dst > MAX_DST) n_dst = MAX_DST;   // scratch safety clamp
    int n_src = in_sizes[0] / DIMD;         // 100000
    int E     = in_sizes[1];                // 600000

    // K0: dtype probe (tiny)
    detect_kernel<<<1, 32>>>(esrc, edst, E, n_src, n_dst);

    // K1: zero scratch (n_dst*128 + n_dst floats)
    zero_kernel<<<640, 512>>>(n_dst);

    // K2: edge aggregation — 1 warp / edge, 8 edges / 256-thread block
    int eb = (E + 7) / 8;
    edge_agg_kernel<<<eb, 256>>>(h, esrc, edst, E);

    // K3: fused mean/concat/GEMM/bias/relu
    int gb = (n_dst + BM - 1) / BM;
    gemm_kernel<<<gb, 256>>>(h, W, b, out, n_dst);
}

// round 5
// speedup vs baseline: 1.0046x; 1.0046x over previous
#include <cuda_runtime.h>
#include <cstdint>

// ---------------------------------------------------------------------------
// MyGraphConv: out = relu([h[:n_dst] || segment_mean(h[edge_src], edge_dst)] @ W.T + b)
//
// R5 plan:
//   K0 detect  : int32 vs int64 edge dtype probe -> g_is64
//   K1 zero    : clear g_cnt / g_cur (20k ints each)
//   K2 hist    : per-dst edge counts (int atomics)
//   K3 scan    : single-block exclusive scan of counts -> g_off
//   K4 scatter : counting-sort edge srcs into CSR (g_csr)
//   K5 gather  : 1 warp / dst, register accumulation of neighbor rows,
//                writes normalized mean directly (no vector atomics!)
//   K6 gemm    : 64x128 tile SGEMM over K=256 (h || g_mean), bias+relu fused,
//                3 CTAs/SM for occupancy.
// ---------------------------------------------------------------------------

#define MAX_DST 32768
#define MAX_E   1048576
#define DIMD    128
#define OUTN    128
#define KDIM    256

__device__ int   g_cnt[MAX_DST];
__device__ int   g_off[MAX_DST];
__device__ int   g_cur[MAX_DST];
__device__ int   g_csr[MAX_E];
__device__ __align__(16) float g_mean[(size_t)MAX_DST * DIMD];
__device__ int   g_is64;

// --- K0: edge index dtype detection -----------------------------------------
// int64 buffers: every sampled 8B word is a valid small index. int32 buffers:
// an 8B read packs two indices; unless the high one is 0 (p~1e-5/sample) the
// value exceeds 2^32. Sample only the first E/2 int64 slots (in-bounds either way).
__global__ void detect_kernel(const void* esrc, const void* edst,
                              int E, int n_src, int n_dst) {
    if (threadIdx.x != 0 || blockIdx.x != 0) return;
    const unsigned long long* p = (const unsigned long long*)esrc;
    const unsigned long long* q = (const unsigned long long*)edst;
    int lim = E >> 1;
    if (lim < 1) { g_is64 = 0; return; }
    int step = (lim > 64) ? (lim / 64) : 1;
    int ok = 1;
    for (int i = 0; i < lim; i += step) {
        if (p[i] >= (unsigned long long)n_src) { ok = 0; break; }
        if (q[i] >= (unsigned long long)n_dst) { ok = 0; break; }
    }
    g_is64 = ok;
}

// --- K1: zero counters -------------------------------------------------------
__global__ void zero_kernel(int n_dst) {
    int i = blockIdx.x * blockDim.x + threadIdx.x;
    int stride = gridDim.x * blockDim.x;
    for (; i < n_dst; i += stride) { g_cnt[i] = 0; g_cur[i] = 0; }
}

// --- K2: histogram of dst indices --------------------------------------------
__global__ void hist_kernel(const void* __restrict__ edst, int E) {
    int i = blockIdx.x * blockDim.x + threadIdx.x;
    if (i >= E) return;
    int d = g_is64 ? (int)((const long long*)edst)[i]
                   : ((const int*)edst)[i];
    atomicAdd(&g_cnt[d], 1);
}

// --- K3: exclusive scan (single block, 1024 threads) --------------------------
__global__ void scan_kernel(int n_dst) {
    __shared__ int part[1024];
    int t = threadIdx.x;
    int chunk = (n_dst + 1023) / 1024;
    int beg = t * chunk;
    int end = beg + chunk; if (end > n_dst) end = n_dst;
    int s = 0;
    for (int i = beg; i < end; i++) s += g_cnt[i];
    part[t] = s;
    __syncthreads();
    // Hillis-Steele inclusive scan
    for (int off = 1; off < 1024; off <<= 1) {
        int v = (t >= off) ? part[t - off] : 0;
        __syncthreads();
        part[t] += v;
        __syncthreads();
    }
    int run = (t > 0) ? part[t - 1] : 0;   // exclusive prefix of this chunk
    for (int i = beg; i < end; i++) {
        g_off[i] = run;
        run += g_cnt[i];
    }
}

// --- K4: scatter srcs into CSR ------------------------------------------------
__global__ void scatter_kernel(const void* __restrict__ esrc,
                               const void* __restrict__ edst, int E) {
    int i = blockIdx.x * blockDim.x + threadIdx.x;
    if (i >= E) return;
    int s, d;
    if (g_is64) {
        s = (int)((const long long*)esrc)[i];
        d = (int)((const long long*)edst)[i];
    } else {
        s = ((const int*)esrc)[i];
        d = ((const int*)edst)[i];
    }
    int pos = atomicAdd(&g_cur[d], 1);
    g_csr[g_off[d] + pos] = s;
}

// --- K5: gather + mean (1 warp per dst, register accumulation) ----------------
__global__ void gather_kernel(const float* __restrict__ h, int n_dst) {
    int w    = (int)((blockIdx.x * (unsigned)blockDim.x + threadIdx.x) >> 5);
    int lane = threadIdx.x & 31;
    if (w >= n_dst) return;

    int beg = g_off[w];
    int cnt = g_cnt[w];
    const float4* __restrict__ h4 = (const float4*)h;

    float4 acc = make_float4(0.f, 0.f, 0.f, 0.f);
    int i = 0;
    for (; i + 4 <= cnt; i += 4) {
        int s0 = g_csr[beg + i + 0];
        int s1 = g_csr[beg + i + 1];
        int s2 = g_csr[beg + i + 2];
        int s3 = g_csr[beg + i + 3];
        float4 v0 = h4[(size_t)s0 * 32 + lane];
        float4 v1 = h4[(size_t)s1 * 32 + lane];
        float4 v2 = h4[(size_t)s2 * 32 + lane];
        float4 v3 = h4[(size_t)s3 * 32 + lane];
        acc.x += (v0.x + v1.x) + (v2.x + v3.x);
        acc.y += (v0.y + v1.y) + (v2.y + v3.y);
        acc.z += (v0.z + v1.z) + (v2.z + v3.z);
        acc.w += (v0.w + v1.w) + (v2.w + v3.w);
    }
    for (; i < cnt; i++) {
        int s = g_csr[beg + i];
        float4 v = h4[(size_t)s * 32 + lane];
        acc.x += v.x; acc.y += v.y; acc.z += v.z; acc.w += v.w;
    }

    float inv = 1.0f / fmaxf((float)cnt, 1.0f);
    acc.x *= inv; acc.y *= inv; acc.z *= inv; acc.w *= inv;
    ((float4*)g_mean)[(size_t)w * 32 + lane] = acc;
}

// --- K6: fused concat + SGEMM + bias + relu -----------------------------------
#define GBM 64
#define GBN 128
#define GBK 32
#define ZS_STRIDE 68    // 64 + 4 pad: float4-aligned, conflict-reduced
#define WS_STRIDE 132   // 128 + 4 pad

__global__ __launch_bounds__(256, 3)
void gemm_kernel(const float* __restrict__ h,
                 const float* __restrict__ W,
                 const float* __restrict__ b,
                 float* __restrict__ out,
                 int n_dst) {
    __shared__ float Zs[GBK][ZS_STRIDE];
    __shared__ float Ws[GBK][WS_STRIDE];

    const int tid  = threadIdx.x;        // 0..255
    const int tx   = tid & 15;           // n group: cols tx*8 .. tx*8+7
    const int ty   = tid >> 4;           // m group: rows ty*4 .. ty*4+3
    const int row0 = blockIdx.x * GBM;

    float acc[4][8];
#pragma unroll
    for (int i = 0; i < 4; i++)
#pragma unroll
        for (int j = 0; j < 8; j++) acc[i][j] = 0.0f;

    for (int kk = 0; kk < KDIM; kk += GBK) {
        const float* __restrict__ src = (kk < DIMD) ? h : g_mean;
        const int kb = (kk < DIMD) ? kk : (kk - DIMD);

        // Z tile: 64 rows x 32 k = 512 float4, 2 per thread
#pragma unroll
        for (int i = 0; i < 2; i++) {
            int f  = tid + i * 256;
            int m  = f >> 3;             // 0..63
            int k4 = (f & 7) * 4;        // 0..28
            int row = row0 + m;
            float4 v = make_float4(0.f, 0.f, 0.f, 0.f);
            if (row < n_dst)
                v = *(const float4*)(src + (size_t)row * DIMD + kb + k4);
            Zs[k4 + 0][m] = v.x;
            Zs[k4 + 1][m] = v.y;
            Zs[k4 + 2][m] = v.z;
            Zs[k4 + 3][m] = v.w;
        }

        // W tile: 128 n x 32 k = 1024 float4, 4 per thread
#pragma unroll
        for (int i = 0; i < 4; i++) {
            int f  = tid + i * 256;
            int n  = f >> 3;             // 0..127
            int k4 = (f & 7) * 4;
            float4 v = *(const float4*)(W + (size_t)n * KDIM + kk + k4);
            Ws[k4 + 0][n] = v.x;
            Ws[k4 + 1][n] = v.y;
            Ws[k4 + 2][n] = v.z;
            Ws[k4 + 3][n] = v.w;
        }

        __syncthreads();

#pragma unroll
        for (int k = 0; k < GBK; k++) {
            float zr[4], wr[8];
            *(float4*)&zr[0] = *(const float4*)&Zs[k][ty * 4];
            *(float4*)&wr[0] = *(const float4*)&Ws[k][tx * 8];
            *(float4*)&wr[4] = *(const float4*)&Ws[k][tx * 8 + 4];
#pragma unroll
            for (int i = 0; i < 4; i++)
#pragma unroll
                for (int j = 0; j < 8; j++)
                    acc[i][j] = fmaf(zr[i], wr[j], acc[i][j]);
        }

        __syncthreads();
    }

    float bias[8];
#pragma unroll
    for (int j = 0; j < 8; j++) bias[j] = b[tx * 8 + j];

#pragma unroll
    for (int i = 0; i < 4; i++) {
        int row = row0 + ty * 4 + i;
        if (row < n_dst) {
            float4 o0, o1;
            o0.x = fmaxf(acc[i][0] + bias[0], 0.f);
            o0.y = fmaxf(acc[i][1] + bias[1], 0.f);
            o0.z = fmaxf(acc[i][2] + bias[2], 0.f);
            o0.w = fmaxf(acc[i][3] + bias[3], 0.f);
            o1.x = fmaxf(acc[i][4] + bias[4], 0.f);
            o1.y = fmaxf(acc[i][5] + bias[5], 0.f);
            o1.z = fmaxf(acc[i][6] + bias[6], 0.f);
            o1.w = fmaxf(acc[i][7] + bias[7], 0.f);
            float* op = out + (size_t)row * OUTN + tx * 8;
            *(float4*)(op)     = o0;
            *(float4*)(op + 4) = o1;
        }
    }
}

// ---------------------------------------------------------------------------
extern "C" void kernel_launch(void* const* d_in, const int* in_sizes, int n_in,
                              void* d_out, int out_size) {
    const float* h    = (const float*)d_in[0];
    const void*  esrc = d_in[1];
    const void*  edst = d_in[2];
    const float* W    = (const float*)d_in[3];
    const float* b    = (const float*)d_in[4];
    float*       out  = (float*)d_out;

    int n_dst = out_size / OUTN;            // 20000
    if (n_dst > MAX_DST) n_dst = MAX_DST;
    int n_src = in_sizes[0] / DIMD;         // 100000
    int E     = in_sizes[1];                // 600000
    if (E > MAX_E) E = MAX_E;

    detect_kernel<<<1, 32>>>(esrc, edst, E, n_src, n_dst);

    zero_kernel<<<(n_dst + 1023) / 1024, 1024>>>(n_dst);

    hist_kernel<<<(E + 255) / 256, 256>>>(edst, E);

    scan_kernel<<<1, 1024>>>(n_dst);

    scatter_kernel<<<(E + 255) / 256, 256>>>(esrc, edst, E);

    gather_kernel<<<(n_dst * 32 + 255) / 256, 256>>>(h, n_dst);

    gemm_kernel<<<(n_dst + GBM - 1) / GBM, 256>>>(h, W, b, out, n_dst);
}

// round 6
// speedup vs baseline: 1.3410x; 1.3349x over previous
#include <cuda_runtime.h>
#include <cstdint>

// ---------------------------------------------------------------------------
// MyGraphConv: out = relu([h[:n_dst] || segment_mean(h[edge_src], edge_dst)] @ W.T + b)
//
// R6 plan:
//   K0 detect  : parallel int32-vs-int64 edge dtype probe -> g_is64
//   K1 zero    : clear g_cnt + overflow counter
//   K2 scatter : bucket edges by dst (CAP=128 slots/dst, overflow -> side list)
//   K3 gather  : 1 warp/dst, register sum of bucket rows, writes mean
//   K3b fixup  : (normally empty) overflow edges red.add into g_mean
//   gemmA      : partial = h_dst @ W[:, :128].T  -- forked onto stream 2,
//                runs CONCURRENTLY with K1..K3b (captured as parallel branch)
//   gemmB      : out = relu(partial + mean @ W[:, 128:].T + b)
// No hist, no scan. Scratch via __device__ globals.
// ---------------------------------------------------------------------------

#define MAX_DST 32768
#define CAP     128
#define MAX_OVF 65536
#define DIMD    128
#define OUTN    128
#define KDIM    256

__device__ int   g_cnt[MAX_DST];
__device__ int   g_csr[(size_t)MAX_DST * CAP];
__device__ int   g_ovf_n;
__device__ int   g_ovf[2 * MAX_OVF];
__device__ __align__(16) float g_mean[(size_t)MAX_DST * DIMD];
__device__ __align__(16) float g_part[(size_t)MAX_DST * OUTN];
__device__ int   g_is64;

// --- K0: edge dtype detection (parallel) --------------------------------------
// int64 buffers: every sampled 8B word is a small valid index. int32 buffers:
// an 8B read packs two indices -> exceeds range unless the high half is 0
// (p ~ 1e-5/sample). Sample only the first E/2 int64 slots (in-bounds for both).
__global__ void detect_kernel(const void* esrc, const void* edst,
                              int E, int n_src, int n_dst) {
    __shared__ int ok;
    int t = threadIdx.x;                       // 64 threads
    if (t == 0) ok = 1;
    __syncthreads();
    int lim = E >> 1;
    if (lim >= 1) {
        int step = (lim > 64) ? (lim / 64) : 1;
        int i = t * step;
        if (i < lim) {
            const unsigned long long* p = (const unsigned long long*)esrc;
            const unsigned long long* q = (const unsigned long long*)edst;
            if (p[i] >= (unsigned long long)n_src ||
                q[i] >= (unsigned long long)n_dst)
                atomicAnd(&ok, 0);
        }
    } else if (t == 0) ok = 0;
    __syncthreads();
    if (t == 0) g_is64 = ok;
}

// --- K1: zero counters ---------------------------------------------------------
__global__ void zero_kernel(int n_dst) {
    int i = blockIdx.x * blockDim.x + threadIdx.x;
    if (i < n_dst) g_cnt[i] = 0;
    if (i == 0) g_ovf_n = 0;
}

// --- K2: bucket scatter ----------------------------------------------------------
__global__ void scatter_kernel(const void* __restrict__ esrc,
                               const void* __restrict__ edst, int E) {
    int i = blockIdx.x * blockDim.x + threadIdx.x;
    if (i >= E) return;
    int s, d;
    if (g_is64) {
        s = (int)((const long long*)esrc)[i];
        d = (int)((const long long*)edst)[i];
    } else {
        s = ((const int*)esrc)[i];
        d = ((const int*)edst)[i];
    }
    int pos = atomicAdd(&g_cnt[d], 1);
    if (pos < CAP) {
        g_csr[(size_t)d * CAP + pos] = s;
    } else {
        int o = atomicAdd(&g_ovf_n, 1);
        if (o < MAX_OVF) { g_ovf[2 * o] = d; g_ovf[2 * o + 1] = s; }
    }
}

// --- K3: gather + mean (1 warp/dst, register accumulation) ----------------------
__global__ void gather_kernel(const float* __restrict__ h, int n_dst) {
    int w    = (int)((blockIdx.x * (unsigned)blockDim.x + threadIdx.x) >> 5);
    int lane = threadIdx.x & 31;
    if (w >= n_dst) return;

    int cnt = g_cnt[w];
    int m = cnt < CAP ? cnt : CAP;
    const int* __restrict__ bkt = g_csr + (size_t)w * CAP;
    const float4* __restrict__ h4 = (const float4*)h;

    float4 acc = make_float4(0.f, 0.f, 0.f, 0.f);
    int i = 0;
    for (; i + 4 <= m; i += 4) {
        int s0 = bkt[i + 0], s1 = bkt[i + 1], s2 = bkt[i + 2], s3 = bkt[i + 3];
        float4 v0 = h4[(size_t)s0 * 32 + lane];
        float4 v1 = h4[(size_t)s1 * 32 + lane];
        float4 v2 = h4[(size_t)s2 * 32 + lane];
        float4 v3 = h4[(size_t)s3 * 32 + lane];
        acc.x += (v0.x + v1.x) + (v2.x + v3.x);
        acc.y += (v0.y + v1.y) + (v2.y + v3.y);
        acc.z += (v0.z + v1.z) + (v2.z + v3.z);
        acc.w += (v0.w + v1.w) + (v2.w + v3.w);
    }
    for (; i < m; i++) {
        int s = bkt[i];
        float4 v = h4[(size_t)s * 32 + lane];
        acc.x += v.x; acc.y += v.y; acc.z += v.z; acc.w += v.w;
    }

    float inv = 1.0f / fmaxf((float)cnt, 1.0f);
    acc.x *= inv; acc.y *= inv; acc.z *= inv; acc.w *= inv;
    ((float4*)g_mean)[(size_t)w * 32 + lane] = acc;
}

// --- K3b: overflow fixup (normally a no-op) -------------------------------------
__global__ void fixup_kernel(const float* __restrict__ h) {
    int n = g_ovf_n;
    if (n > MAX_OVF) n = MAX_OVF;
    int warp = (int)((blockIdx.x * (unsigned)blockDim.x + threadIdx.x) >> 5);
    int lane = threadIdx.x & 31;
    int nwarps = (gridDim.x * blockDim.x) >> 5;
    const float4* __restrict__ h4 = (const float4*)h;
    for (int e = warp; e < n; e += nwarps) {
        int d = g_ovf[2 * e];
        int s = g_ovf[2 * e + 1];
        float inv = 1.0f / fmaxf((float)g_cnt[d], 1.0f);
        float4 v = h4[(size_t)s * 32 + lane];
        float* a = g_mean + (size_t)d * DIMD + lane * 4;
        asm volatile("red.global.add.v4.f32 [%0], {%1,%2,%3,%4};"
                     :: "l"(a), "f"(v.x * inv), "f"(v.y * inv),
                        "f"(v.z * inv), "f"(v.w * inv) : "memory");
    }
}

// --- GEMM halves ------------------------------------------------------------------
#define GBM 64
#define GBN 128
#define GBK 32
#define ZS_STRIDE 68
#define WS_STRIDE 132

// gemmA: part[m][n] = sum_{k<128} h[m][k] * W[n][k]
__global__ __launch_bounds__(256, 3)
void gemmA_kernel(const float* __restrict__ h,
                  const float* __restrict__ W,
                  int n_dst) {
    __shared__ float Zs[GBK][ZS_STRIDE];
    __shared__ float Ws[GBK][WS_STRIDE];

    const int tid  = threadIdx.x;
    const int tx   = tid & 15;
    const int ty   = tid >> 4;
    const int row0 = blockIdx.x * GBM;

    float acc[4][8];
#pragma unroll
    for (int i = 0; i < 4; i++)
#pragma unroll
        for (int j = 0; j < 8; j++) acc[i][j] = 0.0f;

    for (int kk = 0; kk < DIMD; kk += GBK) {
#pragma unroll
        for (int i = 0; i < 2; i++) {
            int f  = tid + i * 256;
            int mm = f >> 3;
            int k4 = (f & 7) * 4;
            int row = row0 + mm;
            float4 v = make_float4(0.f, 0.f, 0.f, 0.f);
            if (row < n_dst)
                v = *(const float4*)(h + (size_t)row * DIMD + kk + k4);
            Zs[k4 + 0][mm] = v.x; Zs[k4 + 1][mm] = v.y;
            Zs[k4 + 2][mm] = v.z; Zs[k4 + 3][mm] = v.w;
        }
#pragma unroll
        for (int i = 0; i < 4; i++) {
            int f  = tid + i * 256;
            int nn = f >> 3;
            int k4 = (f & 7) * 4;
            float4 v = *(const float4*)(W + (size_t)nn * KDIM + kk + k4);
            Ws[k4 + 0][nn] = v.x; Ws[k4 + 1][nn] = v.y;
            Ws[k4 + 2][nn] = v.z; Ws[k4 + 3][nn] = v.w;
        }
        __syncthreads();
#pragma unroll
        for (int k = 0; k < GBK; k++) {
            float zr[4], wr[8];
            *(float4*)&zr[0] = *(const float4*)&Zs[k][ty * 4];
            *(float4*)&wr[0] = *(const float4*)&Ws[k][tx * 8];
            *(float4*)&wr[4] = *(const float4*)&Ws[k][tx * 8 + 4];
#pragma unroll
            for (int i = 0; i < 4; i++)
#pragma unroll
                for (int j = 0; j < 8; j++)
                    acc[i][j] = fmaf(zr[i], wr[j], acc[i][j]);
        }
        __syncthreads();
    }

#pragma unroll
    for (int i = 0; i < 4; i++) {
        int row = row0 + ty * 4 + i;
        if (row < n_dst) {
            float* op = g_part + (size_t)row * OUTN + tx * 8;
            *(float4*)(op)     = make_float4(acc[i][0], acc[i][1], acc[i][2], acc[i][3]);
            *(float4*)(op + 4) = make_float4(acc[i][4], acc[i][5], acc[i][6], acc[i][7]);
        }
    }
}

// gemmB: out[m][n] = relu(part[m][n] + sum_k mean[m][k]*W[n][128+k] + b[n])
__global__ __launch_bounds__(256, 3)
void gemmB_kernel(const float* __restrict__ W,
                  const float* __restrict__ b,
                  float* __restrict__ out,
                  int n_dst) {
    __shared__ float Zs[GBK][ZS_STRIDE];
    __shared__ float Ws[GBK][WS_STRIDE];

    const int tid  = threadIdx.x;
    const int tx   = tid & 15;
    const int ty   = tid >> 4;
    const int row0 = blockIdx.x * GBM;

    float acc[4][8];
#pragma unroll
    for (int i = 0; i < 4; i++)
#pragma unroll
        for (int j = 0; j < 8; j++) acc[i][j] = 0.0f;

    for (int kk = 0; kk < DIMD; kk += GBK) {
#pragma unroll
        for (int i = 0; i < 2; i++) {
            int f  = tid + i * 256;
            int mm = f >> 3;
            int k4 = (f & 7) * 4;
            int row = row0 + mm;
            float4 v = make_float4(0.f, 0.f, 0.f, 0.f);
            if (row < n_dst)
                v = *(const float4*)(g_mean + (size_t)row * DIMD + kk + k4);
            Zs[k4 + 0][mm] = v.x; Zs[k4 + 1][mm] = v.y;
            Zs[k4 + 2][mm] = v.z; Zs[k4 + 3][mm] = v.w;
        }
#pragma unroll
        for (int i = 0; i < 4; i++) {
            int f  = tid + i * 256;
            int nn = f >> 3;
            int k4 = (f & 7) * 4;
            float4 v = *(const float4*)(W + (size_t)nn * KDIM + DIMD + kk + k4);
            Ws[k4 + 0][nn] = v.x; Ws[k4 + 1][nn] = v.y;
            Ws[k4 + 2][nn] = v.z; Ws[k4 + 3][nn] = v.w;
        }
        __syncthreads();
#pragma unroll
        for (int k = 0; k < GBK; k++) {
            float zr[4], wr[8];
            *(float4*)&zr[0] = *(const float4*)&Zs[k][ty * 4];
            *(float4*)&wr[0] = *(const float4*)&Ws[k][tx * 8];
            *(float4*)&wr[4] = *(const float4*)&Ws[k][tx * 8 + 4];
#pragma unroll
            for (int i = 0; i < 4; i++)
#pragma unroll
                for (int j = 0; j < 8; j++)
                    acc[i][j] = fmaf(zr[i], wr[j], acc[i][j]);
        }
        __syncthreads();
    }

    float bias[8];
#pragma unroll
    for (int j = 0; j < 8; j++) bias[j] = b[tx * 8 + j];

#pragma unroll
    for (int i = 0; i < 4; i++) {
        int row = row0 + ty * 4 + i;
        if (row < n_dst) {
            const float* pp = g_part + (size_t)row * OUTN + tx * 8;
            float4 p0 = *(const float4*)(pp);
            float4 p1 = *(const float4*)(pp + 4);
            float4 o0, o1;
            o0.x = fmaxf(acc[i][0] + p0.x + bias[0], 0.f);
            o0.y = fmaxf(acc[i][1] + p0.y + bias[1], 0.f);
            o0.z = fmaxf(acc[i][2] + p0.z + bias[2], 0.f);
            o0.w = fmaxf(acc[i][3] + p0.w + bias[3], 0.f);
            o1.x = fmaxf(acc[i][4] + p1.x + bias[4], 0.f);
            o1.y = fmaxf(acc[i][5] + p1.y + bias[5], 0.f);
            o1.z = fmaxf(acc[i][6] + p1.z + bias[6], 0.f);
            o1.w = fmaxf(acc[i][7] + p1.w + bias[7], 0.f);
            float* op = out + (size_t)row * OUTN + tx * 8;
            *(float4*)(op)     = o0;
            *(float4*)(op + 4) = o1;
        }
    }
}

// ---------------------------------------------------------------------------
extern "C" void kernel_launch(void* const* d_in, const int* in_sizes, int n_in,
                              void* d_out, int out_size) {
    const float* h    = (const float*)d_in[0];
    const void*  esrc = d_in[1];
    const void*  edst = d_in[2];
    const float* W    = (const float*)d_in[3];
    const float* b    = (const float*)d_in[4];
    float*       out  = (float*)d_out;

    int n_dst = out_size / OUTN;            // 20000
    if (n_dst > MAX_DST) n_dst = MAX_DST;
    int n_src = in_sizes[0] / DIMD;         // 100000
    int E     = in_sizes[1];                // 600000

    // Fork a second stream for the independent h_dst @ W1.T GEMM. Created
    // fresh each call (kernel_launch runs only for correctness + capture),
    // so the captured graph gets a genuine parallel branch. No device memory
    // is allocated by stream/event creation.
    cudaStream_t s2 = 0;
    cudaEvent_t evFork = 0, evJoin = 0;
    bool fork_ok =
        (cudaStreamCreateWithFlags(&s2, cudaStreamNonBlocking) == cudaSuccess) &&
        (cudaEventCreateWithFlags(&evFork, cudaEventDisableTiming) == cudaSuccess) &&
        (cudaEventCreateWithFlags(&evJoin, cudaEventDisableTiming) == cudaSuccess);

    int gemm_grid = (n_dst + GBM - 1) / GBM;

    if (fork_ok) {
        cudaEventRecord(evFork, 0);
        cudaStreamWaitEvent(s2, evFork, 0);
        gemmA_kernel<<<gemm_grid, 256, 0, s2>>>(h, W, n_dst);
        cudaEventRecord(evJoin, s2);
    }

    // Aggregation path on the main stream
    detect_kernel<<<1, 64>>>(esrc, edst, E, n_src, n_dst);
    zero_kernel<<<(n_dst + 511) / 512, 512>>>(n_dst);
    scatter_kernel<<<(E + 255) / 256, 256>>>(esrc, edst, E);
    gather_kernel<<<(n_dst * 32 + 255) / 256, 256>>>(h, n_dst);
    fixup_kernel<<<8, 256>>>(h);

    if (fork_ok) {
        cudaStreamWaitEvent((cudaStream_t)0, evJoin, 0);
    } else {
        gemmA_kernel<<<gemm_grid, 256>>>(h, W, n_dst);
    }

    gemmB_kernel<<<gemm_grid, 256>>>(W, b, out, n_dst);
}

// round 10
// speedup vs baseline: 1.3754x; 1.0256x over previous
#include <cuda_runtime.h>
#include <cstdint>

// ---------------------------------------------------------------------------
// MyGraphConv: out = relu([h[:n_dst] || segment_mean(h[edge_src], edge_dst)] @ W.T + b)
//
// R10 plan (tcgen05 unavailable: harness PTX targets sm_103, no 'a' features):
//   K1 init    : zero g_cnt/ovf + parallel int32/int64 dtype probe (one node)
//   K2 scatter : 4 edges/thread bucket scatter (CAP=128, overflow list)
//   K3 gather  : 1 warp/dst, 8-way unrolled register sum -> normalized mean
//   K3b fixup  : overflow edges red.add into g_mean (normally empty)
//   gemmA      : g_part = h_dst @ W[:, :128].T  -- forked stream, overlaps K1..K3b
//   gemmB      : out = relu(g_part + g_mean @ W[:, 128:].T + b)
//   Both GEMMs use packed fma.rn.f32x2 (FFMA2): 2 FMAs/instruction.
// ---------------------------------------------------------------------------

#define MAX_DST 32768
#define CAP     128
#define MAX_OVF 65536
#define DIMD    128
#define OUTN    128
#define KDIM    256

__device__ int   g_cnt[MAX_DST];
__device__ int   g_csr[(size_t)MAX_DST * CAP];
__device__ int   g_ovf_n;
__device__ int   g_ovf[2 * MAX_OVF];
__device__ __align__(16) float g_mean[(size_t)MAX_DST * DIMD];
__device__ __align__(16) float g_part[(size_t)MAX_DST * OUTN];
__device__ int   g_is64;

// --- K1: zero counters + dtype probe ------------------------------------------
// int64 buffers: every sampled 8B word is a small valid index. int32 buffers:
// an 8B read packs two indices -> exceeds range unless the high half is 0
// (p ~ 1e-5/sample). Sample only the first E/2 int64 slots (in-bounds for both).
__global__ void init_kernel(const void* esrc, const void* edst,
                            int E, int n_src, int n_dst) {
    __shared__ int ok;
    if (threadIdx.x == 0) ok = 1;
    __syncthreads();
    int i = blockIdx.x * blockDim.x + threadIdx.x;
    if (i < n_dst) g_cnt[i] = 0;
    if (i == 0) g_ovf_n = 0;
    if (blockIdx.x == 0 && threadIdx.x < 64) {
        int lim = E >> 1;
        if (lim < 1) {
            if (threadIdx.x == 0) atomicAnd(&ok, 0);
        } else {
            int step = (lim > 64) ? (lim / 64) : 1;
            int j = threadIdx.x * step;
            if (j < lim) {
                const unsigned long long* p = (const unsigned long long*)esrc;
                const unsigned long long* q = (const unsigned long long*)edst;
                if (p[j] >= (unsigned long long)n_src ||
                    q[j] >= (unsigned long long)n_dst)
                    atomicAnd(&ok, 0);
            }
        }
    }
    __syncthreads();
    if (blockIdx.x == 0 && threadIdx.x == 0) g_is64 = ok;
}

// --- K2: bucket scatter, 4 edges/thread (independent atomic chains -> MLP) ----
__global__ void scatter_kernel(const void* __restrict__ esrc,
                               const void* __restrict__ edst, int E) {
    int base = (int)((blockIdx.x * (unsigned)blockDim.x + threadIdx.x) * 4u);
    bool is64 = (g_is64 != 0);
    int s[4], d[4];
#pragma unroll
    for (int j = 0; j < 4; j++) {
        int i = base + j;
        if (i < E) {
            if (is64) {
                s[j] = (int)((const long long*)esrc)[i];
                d[j] = (int)((const long long*)edst)[i];
            } else {
                s[j] = ((const int*)esrc)[i];
                d[j] = ((const int*)edst)[i];
            }
        } else d[j] = -1;
    }
    int pos[4];
#pragma unroll
    for (int j = 0; j < 4; j++)
        pos[j] = (d[j] >= 0) ? atomicAdd(&g_cnt[d[j]], 1) : 0;
#pragma unroll
    for (int j = 0; j < 4; j++) {
        if (d[j] >= 0) {
            if (pos[j] < CAP) {
                g_csr[(size_t)d[j] * CAP + pos[j]] = s[j];
            } else {
                int o = atomicAdd(&g_ovf_n, 1);
                if (o < MAX_OVF) { g_ovf[2 * o] = d[j]; g_ovf[2 * o + 1] = s[j]; }
            }
        }
    }
}

// --- K3: gather + mean (1 warp/dst, 8-way unroll) ------------------------------
__global__ void gather_kernel(const float* __restrict__ h, int n_dst) {
    int w    = (int)((blockIdx.x * (unsigned)blockDim.x + threadIdx.x) >> 5);
    int lane = threadIdx.x & 31;
    if (w >= n_dst) return;

    int cnt = g_cnt[w];
    int m = cnt < CAP ? cnt : CAP;
    const int* __restrict__ bkt = g_csr + (size_t)w * CAP;
    const float4* __restrict__ h4 = (const float4*)h;

    float4 acc = make_float4(0.f, 0.f, 0.f, 0.f);
    int i = 0;
    for (; i + 8 <= m; i += 8) {
        float4 v[8];
#pragma unroll
        for (int j = 0; j < 8; j++) {
            int s = bkt[i + j];
            v[j] = h4[(size_t)s * 32 + lane];
        }
#pragma unroll
        for (int j = 0; j < 8; j++) {
            acc.x += v[j].x; acc.y += v[j].y; acc.z += v[j].z; acc.w += v[j].w;
        }
    }
    for (; i < m; i++) {
        int s = bkt[i];
        float4 v = h4[(size_t)s * 32 + lane];
        acc.x += v.x; acc.y += v.y; acc.z += v.z; acc.w += v.w;
    }

    float inv = 1.0f / fmaxf((float)cnt, 1.0f);
    acc.x *= inv; acc.y *= inv; acc.z *= inv; acc.w *= inv;
    ((float4*)g_mean)[(size_t)w * 32 + lane] = acc;
}

// --- K3b: overflow fixup (normally no-op) --------------------------------------
__global__ void fixup_kernel(const float* __restrict__ h) {
    int n = g_ovf_n;
    if (n > MAX_OVF) n = MAX_OVF;
    if (n == 0) return;
    int warp = (int)((blockIdx.x * (unsigned)blockDim.x + threadIdx.x) >> 5);
    int lane = threadIdx.x & 31;
    int nwarps = (gridDim.x * blockDim.x) >> 5;
    const float4* __restrict__ h4 = (const float4*)h;
    for (int e = warp; e < n; e += nwarps) {
        int d = g_ovf[2 * e];
        int s = g_ovf[2 * e + 1];
        float inv = 1.0f / fmaxf((float)g_cnt[d], 1.0f);
        float4 v = h4[(size_t)s * 32 + lane];
        float* a = g_mean + (size_t)d * DIMD + lane * 4;
        asm volatile("red.global.add.v4.f32 [%0], {%1,%2,%3,%4};"
                     :: "l"(a), "f"(v.x * inv), "f"(v.y * inv),
                        "f"(v.z * inv), "f"(v.w * inv) : "memory");
    }
}

// --- GEMM halves: 64x128 tile, K=128 each, packed f32x2 FMA ---------------------
#define GBM 64
#define GBN 128
#define GBK 32
#define ZS_STRIDE 68
#define WS_STRIDE 132

union F4U2 { float4 f; unsigned long long u[2]; };

#define PACK_BCAST(dst, src) \
    asm("mov.b64 %0, {%1, %1};" : "=l"(dst) : "f"(src))
#define FFMA2(acc, a2, b2) \
    asm("fma.rn.f32x2 %0, %1, %2, %0;" : "+l"(acc) : "l"(a2), "l"(b2))
#define UNPACK2(lo, hi, src) \
    asm("mov.b64 {%0, %1}, %2;" : "=f"(lo), "=f"(hi) : "l"(src))

// Shared GEMM body. srcZ: 64x128 f32 rows (row stride DIMD). Wcol0: starting
// column of W (0 for gemmA, 128 for gemmB). Accumulates into acc[4][4] (f32x2).
__device__ __forceinline__ void gemm_body(
    const float* __restrict__ srcZ, const float* __restrict__ W, int Wcol0,
    float (*Zs)[ZS_STRIDE], float (*Ws)[WS_STRIDE],
    unsigned long long acc[4][4], int row0, int n_dst, int tid, int tx, int ty) {

    for (int kk = 0; kk < DIMD; kk += GBK) {
#pragma unroll
        for (int i = 0; i < 2; i++) {
            int f  = tid + i * 256;
            int mm = f >> 3;
            int k4 = (f & 7) * 4;
            int row = row0 + mm;
            float4 v = make_float4(0.f, 0.f, 0.f, 0.f);
            if (row < n_dst)
                v = *(const float4*)(srcZ + (size_t)row * DIMD + kk + k4);
            Zs[k4 + 0][mm] = v.x; Zs[k4 + 1][mm] = v.y;
            Zs[k4 + 2][mm] = v.z; Zs[k4 + 3][mm] = v.w;
        }
#pragma unroll
        for (int i = 0; i < 4; i++) {
            int f  = tid + i * 256;
            int nn = f >> 3;
            int k4 = (f & 7) * 4;
            float4 v = *(const float4*)(W + (size_t)nn * KDIM + Wcol0 + kk + k4);
            Ws[k4 + 0][nn] = v.x; Ws[k4 + 1][nn] = v.y;
            Ws[k4 + 2][nn] = v.z; Ws[k4 + 3][nn] = v.w;
        }
        __syncthreads();

#pragma unroll
        for (int k = 0; k < GBK; k++) {
            float zr[4];
            *(float4*)&zr[0] = *(const float4*)&Zs[k][ty * 4];
            F4U2 w0, w1;
            w0.f = *(const float4*)&Ws[k][tx * 8];
            w1.f = *(const float4*)&Ws[k][tx * 8 + 4];
            unsigned long long z2[4];
#pragma unroll
            for (int i = 0; i < 4; i++) PACK_BCAST(z2[i], zr[i]);
#pragma unroll
            for (int i = 0; i < 4; i++) {
                FFMA2(acc[i][0], z2[i], w0.u[0]);
                FFMA2(acc[i][1], z2[i], w0.u[1]);
                FFMA2(acc[i][2], z2[i], w1.u[0]);
                FFMA2(acc[i][3], z2[i], w1.u[1]);
            }
        }
        __syncthreads();
    }
}

// gemmA: g_part = h_dst @ W[:, :128].T
__global__ __launch_bounds__(256, 3)
void gemmA_kernel(const float* __restrict__ h,
                  const float* __restrict__ W,
                  int n_dst) {
    __shared__ float Zs[GBK][ZS_STRIDE];
    __shared__ float Ws[GBK][WS_STRIDE];
    const int tid  = threadIdx.x;
    const int tx   = tid & 15;
    const int ty   = tid >> 4;
    const int row0 = blockIdx.x * GBM;

    unsigned long long acc[4][4];
#pragma unroll
    for (int i = 0; i < 4; i++)
#pragma unroll
        for (int j = 0; j < 4; j++) acc[i][j] = 0ull;

    gemm_body(h, W, 0, Zs, Ws, acc, row0, n_dst, tid, tx, ty);

#pragma unroll
    for (int i = 0; i < 4; i++) {
        int row = row0 + ty * 4 + i;
        if (row < n_dst) {
            float4 o0, o1;
            UNPACK2(o0.x, o0.y, acc[i][0]);
            UNPACK2(o0.z, o0.w, acc[i][1]);
            UNPACK2(o1.x, o1.y, acc[i][2]);
            UNPACK2(o1.z, o1.w, acc[i][3]);
            float* op = g_part + (size_t)row * OUTN + tx * 8;
            *(float4*)(op)     = o0;
            *(float4*)(op + 4) = o1;
        }
    }
}

// gemmB: out = relu(g_part + g_mean @ W[:, 128:].T + b)
__global__ __launch_bounds__(256, 3)
void gemmB_kernel(const float* __restrict__ W,
                  const float* __restrict__ b,
                  float* __restrict__ out,
                  int n_dst) {
    __shared__ float Zs[GBK][ZS_STRIDE];
    __shared__ float Ws[GBK][WS_STRIDE];
    const int tid  = threadIdx.x;
    const int tx   = tid & 15;
    const int ty   = tid >> 4;
    const int row0 = blockIdx.x * GBM;

    unsigned long long acc[4][4];
#pragma unroll
    for (int i = 0; i < 4; i++)
#pragma unroll
        for (int j = 0; j < 4; j++) acc[i][j] = 0ull;

    gemm_body(g_mean, W, DIMD, Zs, Ws, acc, row0, n_dst, tid, tx, ty);

    float bias[8];
#pragma unroll
    for (int j = 0; j < 8; j++) bias[j] = b[tx * 8 + j];

#pragma unroll
    for (int i = 0; i < 4; i++) {
        int row = row0 + ty * 4 + i;
        if (row < n_dst) {
            float a[8];
            UNPACK2(a[0], a[1], acc[i][0]);
            UNPACK2(a[2], a[3], acc[i][1]);
            UNPACK2(a[4], a[5], acc[i][2]);
            UNPACK2(a[6], a[7], acc[i][3]);
            const float* pp = g_part + (size_t)row * OUTN + tx * 8;
            float4 p0 = *(const float4*)(pp);
            float4 p1 = *(const float4*)(pp + 4);
            float4 o0, o1;
            o0.x = fmaxf(a[0] + p0.x + bias[0], 0.f);
            o0.y = fmaxf(a[1] + p0.y + bias[1], 0.f);
            o0.z = fmaxf(a[2] + p0.z + bias[2], 0.f);
            o0.w = fmaxf(a[3] + p0.w + bias[3], 0.f);
            o1.x = fmaxf(a[4] + p1.x + bias[4], 0.f);
            o1.y = fmaxf(a[5] + p1.y + bias[5], 0.f);
            o1.z = fmaxf(a[6] + p1.z + bias[6], 0.f);
            o1.w = fmaxf(a[7] + p1.w + bias[7], 0.f);
            float* op = out + (size_t)row * OUTN + tx * 8;
            *(float4*)(op)     = o0;
            *(float4*)(op + 4) = o1;
        }
    }
}

// ---------------------------------------------------------------------------
extern "C" void kernel_launch(void* const* d_in, const int* in_sizes, int n_in,
                              void* d_out, int out_size) {
    const float* h    = (const float*)d_in[0];
    const void*  esrc = d_in[1];
    const void*  edst = d_in[2];
    const float* W    = (const float*)d_in[3];
    const float* b    = (const float*)d_in[4];
    float*       out  = (float*)d_out;

    int n_dst = out_size / OUTN;            // 20000
    if (n_dst > MAX_DST) n_dst = MAX_DST;
    int n_src = in_sizes[0] / DIMD;         // 100000
    int E     = in_sizes[1];                // 600000

    // Fork a second stream for the independent h_dst @ W0.T GEMM so the
    // captured graph gets a parallel branch (no device memory allocated).
    cudaStream_t s2 = 0;
    cudaEvent_t evFork = 0, evJoin = 0;
    bool fork_ok =
        (cudaStreamCreateWithFlags(&s2, cudaStreamNonBlocking) == cudaSuccess) &&
        (cudaEventCreateWithFlags(&evFork, cudaEventDisableTiming) == cudaSuccess) &&
        (cudaEventCreateWithFlags(&evJoin, cudaEventDisableTiming) == cudaSuccess);

    int gemm_grid = (n_dst + GBM - 1) / GBM;

    if (fork_ok) {
        cudaEventRecord(evFork, 0);
        cudaStreamWaitEvent(s2, evFork, 0);
        gemmA_kernel<<<gemm_grid, 256, 0, s2>>>(h, W, n_dst);
        cudaEventRecord(evJoin, s2);
    }

    // Aggregation path on the main stream
    init_kernel<<<(n_dst + 511) / 512, 512>>>(esrc, edst, E, n_src, n_dst);
    scatter_kernel<<<(E + 1023) / 1024, 256>>>(esrc, edst, E);
    gather_kernel<<<(n_dst * 32 + 255) / 256, 256>>>(h, n_dst);
    fixup_kernel<<<8, 256>>>(h);

    if (fork_ok) {
        cudaStreamWaitEvent((cudaStream_t)0, evJoin, 0);
    } else {
        gemmA_kernel<<<gemm_grid, 256>>>(h, W, n_dst);
    }

    gemmB_kernel<<<gemm_grid, 256>>>(W, b, out, n_dst);
}